// round 7
// baseline (speedup 1.0000x reference)
#include <cuda_runtime.h>
#include <math.h>

// BoundaryLoss: exact squared-EDT via separable min-convolution.
// k_wh:    fused targets->ballot W-distance + windowed H min-conv in one
//          smem tile per (b, d-slice, cls). Packed u32 (pos|neg<<16) out.
// k_fuse_d: windowed D min-conv fused with softmax + signed-dist + reduce.
// Shapes: B=2, C=3, D=H=W=96.

#define N2 9216           // 96*96
#define N3 884736         // 96^3
#define SENTI 65535
#define THRSF 32768.0f    // real results <= 27075 < 32768 <= sentinel-derived

__device__ unsigned g_pack[4 * N3];   // 14.2 MB packed scratch
__device__ float g_part[1152];
__device__ int   g_cnt[4];
__device__ int   g_is32;

// ------------------------------------------------------------- dtype detect
__global__ void k_detect(const int* __restrict__ t32) {
    if (threadIdx.x < 4) g_cnt[threadIdx.x] = 0;
    int any = 0;
    #pragma unroll
    for (int u = 0; u < 16; u++) {
        int k = threadIdx.x + 256 * u;
        if (t32[2 * k + 1] != 0) any = 1;
    }
    int r = __syncthreads_or(any);
    if (threadIdx.x == 0) g_is32 = r ? 1 : 0;
}

// ---------------------------------------------- nearest zero bit in 96 bits
__device__ __forceinline__ int near_zero_dist(unsigned z0, unsigned z1, unsigned z2,
                                              int w, int r) {
    unsigned lowm = (2u << r) - 1u;
    unsigned him  = 0xffffffffu << r;
    int dl = 1000, dr = 1000;
    if (w == 0) {
        unsigned u = z0 & lowm;
        if (u) dl = r - (31 - __clz(u));
        unsigned v = z0 & him;
        if (v)       dr = (__ffs(v) - 1) - r;
        else if (z1) dr = 32 - r + (__ffs(z1) - 1);
        else if (z2) dr = 64 - r + (__ffs(z2) - 1);
    } else if (w == 1) {
        unsigned u = z1 & lowm;
        if (u)       dl = r - (31 - __clz(u));
        else if (z0) dl = r + 1 + __clz(z0);
        unsigned v = z1 & him;
        if (v)       dr = (__ffs(v) - 1) - r;
        else if (z2) dr = 32 - r + (__ffs(z2) - 1);
    } else {
        unsigned u = z2 & lowm;
        if (u)       dl = r - (31 - __clz(u));
        else if (z1) dl = r + 1 + __clz(z1);
        else if (z0) dl = r + 33 + __clz(z0);
        unsigned v = z2 & him;
        if (v) dr = (__ffs(v) - 1) - r;
    }
    return min(dl, dr);
}

__device__ __forceinline__ int win_i(int m) {
    if (m >= SENTI) return 95;
    return min(95, (int)floorf(sqrtf((float)m)) + 1);
}

// -------------------------------------------------- fused W + H pass
// Grid: 2(b) * 96(d) * 2(cls) = 384 blocks x 512 (all resident in one wave).
// Phase 1: one warp per h-line: ballots -> W nearest-zero distances for both
//          polarities; store packed (dp2+h2 | dn2+h2<<16, sat 65535) into a
//          transposed smem tile [w*97 + h] (conflict-free both phases).
// Phase 2: windowed min-conv along h per w column; pack + coalesced store.
__global__ void __launch_bounds__(512, 3) k_wh(const void* __restrict__ tptr) {
    __shared__ unsigned tile[96 * 97];   // 37.2 KB
    __shared__ int smx, scnt;
    int bid = blockIdx.x;
    int b = bid / 192, rem = bid % 192;
    int d = rem >> 1, cls = rem & 1;
    int clsv = cls + 1;
    int lane = threadIdx.x & 31, wid = threadIdx.x >> 5;   // 16 warps
    int tbase = b * N3 + d * N2;

    if (threadIdx.x == 0) { smx = 0; scnt = 0; }
    __syncthreads();

    int mx = 0, cnt = 0;
    for (int h = wid; h < 96; h += 16) {
        int t0, t1, t2;
        if (g_is32) {
            const int* T = (const int*)tptr + tbase + h * 96;
            t0 = T[lane]; t1 = T[lane + 32]; t2 = T[lane + 64];
        } else {
            const long long* T = (const long long*)tptr + tbase + h * 96;
            t0 = (int)T[lane]; t1 = (int)T[lane + 32]; t2 = (int)T[lane + 64];
        }
        unsigned m0 = __ballot_sync(0xffffffffu, t0 == clsv);
        unsigned m1 = __ballot_sync(0xffffffffu, t1 == clsv);
        unsigned m2 = __ballot_sync(0xffffffffu, t2 == clsv);
        cnt += __popc(m0) + __popc(m1) + __popc(m2);
        int h2 = h * h;
        #pragma unroll
        for (int w = 0; w < 3; w++) {
            int dp = near_zero_dist(~m0, ~m1, ~m2, w, lane);
            int dn = near_zero_dist(m0, m1, m2, w, lane);
            int fp = (dp > 95) ? SENTI : dp * dp;
            int fn = (dn > 95) ? SENTI : dn * dn;
            mx = max(mx, max(fp, fn));
            unsigned pk = (unsigned)min(fp + h2, SENTI)
                        | ((unsigned)min(fn + h2, SENTI) << 16);
            tile[(lane + 32 * w) * 97 + h] = pk;
        }
    }
    #pragma unroll
    for (int off = 16; off; off >>= 1)
        mx = max(mx, __shfl_xor_sync(0xffffffffu, mx, off));
    if (lane == 0) {
        atomicMax(&smx, mx);
        atomicAdd(&scnt, cnt);      // lane0 holds only its own cnt? no: cnt is per-thread
    }
    // cnt above was accumulated per-thread but only counted by ballots once per
    // warp (all lanes have same m words) -> popc identical across lanes; lane0's
    // cnt is the warp's correct per-line sum. OK.
    __syncthreads();
    if (threadIdx.x == 0) atomicAdd(&g_cnt[b * 2 + cls], scnt);

    int R = win_i(smx);
    int tx = threadIdx.x & 31, ty = threadIdx.x >> 5;
    int i0 = ty * 6;
    int j0 = max(0, i0 - R), j1 = min(95, i0 + 5 + R);

    unsigned* outv = g_pack + (size_t)(b * 2 + cls) * N3 + d * N2;
    float fi[6];
    #pragma unroll
    for (int k = 0; k < 6; k++) fi[k] = (float)(i0 + k);

    #pragma unroll
    for (int c = 0; c < 3; c++) {
        int w = tx + 32 * c;
        const unsigned* col = tile + w * 97;
        float v0[6], v1[6];
        #pragma unroll
        for (int k = 0; k < 6; k++) { v0[k] = 3.0e38f; v1[k] = 3.0e38f; }
        float m2a = -2.0f * (float)j0;
        int j = j0;
        for (; j + 1 <= j1; j += 2) {
            unsigned ua = col[j], ub = col[j + 1];
            float a0 = (float)(ua & 0xffffu), a1 = (float)(ua >> 16);
            float b0 = (float)(ub & 0xffffu), b1 = (float)(ub >> 16);
            float m2b = m2a - 2.0f;
            #pragma unroll
            for (int k = 0; k < 6; k++) {
                v0[k] = fminf(v0[k], fmaf(m2a, fi[k], a0));
                v1[k] = fminf(v1[k], fmaf(m2a, fi[k], a1));
                v0[k] = fminf(v0[k], fmaf(m2b, fi[k], b0));
                v1[k] = fminf(v1[k], fmaf(m2b, fi[k], b1));
            }
            m2a -= 4.0f;
        }
        if (j == j1) {
            unsigned ua = col[j];
            float a0 = (float)(ua & 0xffffu), a1 = (float)(ua >> 16);
            #pragma unroll
            for (int k = 0; k < 6; k++) {
                v0[k] = fminf(v0[k], fmaf(m2a, fi[k], a0));
                v1[k] = fminf(v1[k], fmaf(m2a, fi[k], a1));
            }
        }
        #pragma unroll
        for (int k = 0; k < 6; k++) {
            float i2 = fi[k] * fi[k];
            float r0 = v0[k] + i2;
            float r1 = v1[k] + i2;
            unsigned e0 = (r0 >= THRSF) ? (unsigned)SENTI : (unsigned)__float2int_rn(r0);
            unsigned e1 = (r1 >= THRSF) ? (unsigned)SENTI : (unsigned)__float2int_rn(r1);
            outv[(i0 + k) * 96 + w] = e0 | (e1 << 16);
        }
    }
}

// ------------------------------------------- fused D pass + softmax reduce
// Grid: 4 packed vols (b,cls) * 96 h-slices * 3 w-chunks = 1152 blocks x 512.
__global__ void __launch_bounds__(512, 3) k_fuse_d(const float* __restrict__ logits) {
    __shared__ float sh0[96 * 32];
    __shared__ float sh1[96 * 32];
    __shared__ int smx0, smx1;
    __shared__ float swred[16];
    int bid = blockIdx.x;
    int vb = bid / 288, rem = bid % 288;
    int s = rem / 3, wc = rem % 3;
    int b = vb >> 1, cls = vb & 1;
    int tx = threadIdx.x & 31, ty = threadIdx.x >> 5;
    unsigned nbase = (unsigned)s * 96 + wc * 32 + tx;   // voxel idx: + d*N2

    if (threadIdx.x == 0) { smx0 = 0; smx1 = 0; }
    __syncthreads();

    const unsigned* p = g_pack + (size_t)vb * N3 + nbase;
    int mx0 = 0, mx1 = 0;
    #pragma unroll
    for (int r = ty; r < 96; r += 16) {
        unsigned u = p[(size_t)r * N2];
        int lo = (int)(u & 0xffffu), hi = (int)(u >> 16);
        mx0 = max(mx0, lo); mx1 = max(mx1, hi);
        float r2 = (float)(r * r);
        sh0[r * 32 + tx] = (float)lo + r2;
        sh1[r * 32 + tx] = (float)hi + r2;
    }
    #pragma unroll
    for (int off = 16; off; off >>= 1) {
        mx0 = max(mx0, __shfl_xor_sync(0xffffffffu, mx0, off));
        mx1 = max(mx1, __shfl_xor_sync(0xffffffffu, mx1, off));
    }
    if (tx == 0) { atomicMax(&smx0, mx0); atomicMax(&smx1, mx1); }
    __syncthreads();
    int R = max(win_i(smx0), win_i(smx1));

    int i0 = ty * 6;
    int j0 = max(0, i0 - R), j1 = min(95, i0 + 5 + R);
    float v0[6], v1[6], fi[6];
    #pragma unroll
    for (int k = 0; k < 6; k++) { v0[k] = 3.0e38f; v1[k] = 3.0e38f; fi[k] = (float)(i0 + k); }

    {
        const float* s0 = sh0 + tx;
        const float* s1 = sh1 + tx;
        float m2a = -2.0f * (float)j0;
        int j = j0;
        for (; j + 1 <= j1; j += 2) {
            float a0 = s0[j * 32], a1 = s1[j * 32];
            float b0 = s0[j * 32 + 32], b1 = s1[j * 32 + 32];
            float m2b = m2a - 2.0f;
            #pragma unroll
            for (int k = 0; k < 6; k++) {
                v0[k] = fminf(v0[k], fmaf(m2a, fi[k], a0));
                v1[k] = fminf(v1[k], fmaf(m2a, fi[k], a1));
                v0[k] = fminf(v0[k], fmaf(m2b, fi[k], b0));
                v1[k] = fminf(v1[k], fmaf(m2b, fi[k], b1));
            }
            m2a -= 4.0f;
        }
        if (j == j1) {
            float a0 = s0[j * 32], a1 = s1[j * 32];
            #pragma unroll
            for (int k = 0; k < 6; k++) {
                v0[k] = fminf(v0[k], fmaf(m2a, fi[k], a0));
                v1[k] = fminf(v1[k], fmaf(m2a, fi[k], a1));
            }
        }
    }

    // epilogue: sd = sqrt(neg) - sqrt(pos); softmax prob of this class; gate
    float gate = g_cnt[b * 2 + cls] > 0 ? 1.f : 0.f;
    const float* L = logits + (size_t)b * 3 * N3 + nbase + (size_t)i0 * N2;
    float acc = 0.f;
    #pragma unroll
    for (int k = 0; k < 6; k++) {
        float i2 = fi[k] * fi[k];
        float r0 = v0[k] + i2;
        float r1 = v1[k] + i2;
        float f0 = (r0 >= THRSF) ? 1e8f : r0;
        float f1 = (r1 >= THRSF) ? 1e8f : r1;
        float sd = sqrtf(f1) - sqrtf(f0);
        float l0 = L[0], l1 = L[(size_t)N3], l2 = L[(size_t)2 * N3];
        L += N2;
        float m = fmaxf(l0, fmaxf(l1, l2));
        float e0 = __expf(l0 - m), e1 = __expf(l1 - m), e2 = __expf(l2 - m);
        float ec = cls ? e2 : e1;
        acc += (ec / (e0 + e1 + e2)) * sd;
    }
    acc *= gate;

    #pragma unroll
    for (int off = 16; off; off >>= 1)
        acc += __shfl_down_sync(0xffffffffu, acc, off);
    if (tx == 0) swred[ty] = acc;
    __syncthreads();
    if (threadIdx.x == 0) {
        float t = 0.f;
        #pragma unroll
        for (int i = 0; i < 16; i++) t += swred[i];
        g_part[bid] = t;
    }
}

// ---------------------------------------------------------------- final
__global__ void k_final(float* __restrict__ out) {
    __shared__ double sm[256];
    double s = 0.0;
    for (int i = threadIdx.x; i < 1152; i += 256) s += (double)g_part[i];
    sm[threadIdx.x] = s;
    __syncthreads();
    #pragma unroll
    for (int off = 128; off > 0; off >>= 1) {
        if (threadIdx.x < off) sm[threadIdx.x] += sm[threadIdx.x + off];
        __syncthreads();
    }
    if (threadIdx.x == 0)
        out[0] = (float)(sm[0] / (2.0 * (double)N3));
}

// ---------------------------------------------------------------- launch
extern "C" void kernel_launch(void* const* d_in, const int* in_sizes, int n_in,
                              void* d_out, int out_size) {
    const float* logits = (const float*)d_in[0];
    const void*  targets = d_in[1];
    float* out = (float*)d_out;
    (void)in_sizes; (void)n_in; (void)out_size;

    k_detect<<<1, 256>>>((const int*)targets);
    k_wh<<<384, 512>>>(targets);
    k_fuse_d<<<1152, 512>>>(logits);
    k_final<<<1, 256>>>(out);
}

// round 9
// speedup vs baseline: 1.1578x; 1.1578x over previous
#include <cuda_runtime.h>
#include <math.h>

// BoundaryLoss: exact squared-EDT via separable min-convolution.
// R6 structure (proven 66us) minus the two tiny kernels:
//  - dtype detect folded into each k_binw block (L2-hot probe)
//    [R8 bug fixed: nonzero odd int32 words => int32, NOT int64]
//  - final reduction via deterministic fixed-point u64 atomic + ticket,
//    counts reduced by pass_h block 0.
// Shapes: B=2, C=3, D=H=W=96.

#define N2 9216           // 96*96
#define N3 884736         // 96^3
#define SENTI 65535
#define THRSF 32768.0f    // real <= 27075 < 32768 <= sentinel-derived

__device__ unsigned g_pack[4 * N3];    // 14.2 MB packed scratch (pos|neg<<16)
__device__ unsigned g_cntpart[2304];   // per-binw-block packed counts
__device__ int      g_cnt[4];
__device__ unsigned long long g_sum;   // fixed-point (x 2^24) loss numerator
__device__ unsigned g_tick = 0;        // monotonic ticket (mod 1152 per launch)

// ---------------------------------------------- nearest zero bit in 96 bits
__device__ __forceinline__ int near_zero_dist(unsigned z0, unsigned z1, unsigned z2,
                                              int w, int r) {
    unsigned lowm = (2u << r) - 1u;
    unsigned him  = 0xffffffffu << r;
    int dl = 1000, dr = 1000;
    if (w == 0) {
        unsigned u = z0 & lowm;
        if (u) dl = r - (31 - __clz(u));
        unsigned v = z0 & him;
        if (v)       dr = (__ffs(v) - 1) - r;
        else if (z1) dr = 32 - r + (__ffs(z1) - 1);
        else if (z2) dr = 64 - r + (__ffs(z2) - 1);
    } else if (w == 1) {
        unsigned u = z1 & lowm;
        if (u)       dl = r - (31 - __clz(u));
        else if (z0) dl = r + 1 + __clz(z0);
        unsigned v = z1 & him;
        if (v)       dr = (__ffs(v) - 1) - r;
        else if (z2) dr = 32 - r + (__ffs(z2) - 1);
    } else {
        unsigned u = z2 & lowm;
        if (u)       dl = r - (31 - __clz(u));
        else if (z1) dl = r + 1 + __clz(z1);
        else if (z0) dl = r + 33 + __clz(z0);
        unsigned v = z2 & him;
        if (v) dr = (__ffs(v) - 1) - r;
    }
    return min(dl, dr);
}

__device__ __forceinline__ unsigned enc_d(int d) {
    return (d > 95) ? (unsigned)SENTI : (unsigned)(d * d);
}

__device__ __forceinline__ int win_i(int m) {
    if (m >= SENTI) return 95;
    return min(95, (int)floorf(sqrtf((float)m)) + 1);
}

// ------------------------------------------------- fused init + W-axis pass
// Grid: 2304 blocks x 256 (8 lines/block). Per-block dtype probe:
// int64 targets in [0,2] -> all odd int32 words ZERO. Nonzero odd word
// (target values 1/2 in the high half of a pair) -> int32 layout.
__global__ void __launch_bounds__(256) k_binw(const void* __restrict__ tptr) {
    __shared__ int sc[2];
    const int* t32 = (const int*)tptr;
    if (threadIdx.x < 2) sc[threadIdx.x] = 0;
    int any = 0;
    if (threadIdx.x < 64) any = (t32[2 * threadIdx.x + 1] != 0);
    int nz = __syncthreads_or(any);       // also orders sc init
    int is64 = !nz;                       // all-zero odd words => int64

    int wid = threadIdx.x >> 5, l = threadIdx.x & 31;
    int L = blockIdx.x * 8 + wid;
    int b = L / 9216;
    int n = L - b * 9216;
    int base = b * N3 + n * 96;

    int t0, t1, t2;
    if (!is64) {
        const int* T = t32;
        t0 = T[base + l]; t1 = T[base + l + 32]; t2 = T[base + l + 64];
    } else {
        const long long* T = (const long long*)tptr;
        t0 = (int)T[base + l]; t1 = (int)T[base + l + 32]; t2 = (int)T[base + l + 64];
    }
    unsigned m1_0 = __ballot_sync(0xffffffffu, t0 == 1);
    unsigned m1_1 = __ballot_sync(0xffffffffu, t1 == 1);
    unsigned m1_2 = __ballot_sync(0xffffffffu, t2 == 1);
    unsigned m2_0 = __ballot_sync(0xffffffffu, t0 == 2);
    unsigned m2_1 = __ballot_sync(0xffffffffu, t1 == 2);
    unsigned m2_2 = __ballot_sync(0xffffffffu, t2 == 2);

    if (l == 0) {
        atomicAdd(&sc[0], __popc(m1_0) + __popc(m1_1) + __popc(m1_2));
        atomicAdd(&sc[1], __popc(m2_0) + __popc(m2_1) + __popc(m2_2));
    }

    #pragma unroll
    for (int cls = 0; cls < 2; cls++) {
        unsigned m0 = cls ? m2_0 : m1_0;
        unsigned m1 = cls ? m2_1 : m1_1;
        unsigned m2 = cls ? m2_2 : m1_2;
        unsigned* out = g_pack + (size_t)(b * 2 + cls) * N3 + n * 96;
        #pragma unroll
        for (int w = 0; w < 3; w++) {
            int dp = near_zero_dist(~m0, ~m1, ~m2, w, l);
            int dn = near_zero_dist(m0, m1, m2, w, l);
            out[l + 32 * w] = enc_d(dp) | (enc_d(dn) << 16);
        }
    }
    __syncthreads();
    if (threadIdx.x == 0)
        g_cntpart[blockIdx.x] = (unsigned)sc[0] | ((unsigned)sc[1] << 16);
}

// ---------------------------------------------------------------- H pass
// Grid: 4 packed vols * 96 d-slices * 3 w-chunks = 1152 blocks x 512.
// Block 0 additionally reduces g_cntpart -> g_cnt and zeroes g_sum.
__global__ void __launch_bounds__(512, 3) k_pass_h() {
    __shared__ float sh0[96 * 32];
    __shared__ float sh1[96 * 32];
    __shared__ int smx0, smx1;
    __shared__ int red[4];
    int bid = blockIdx.x;

    if (threadIdx.x == 0) { smx0 = 0; smx1 = 0; }
    if (threadIdx.x < 4) red[threadIdx.x] = 0;
    __syncthreads();

    if (bid == 0) {
        int c00 = 0, c01 = 0, c10 = 0, c11 = 0;
        for (int i = threadIdx.x; i < 2304; i += 512) {
            unsigned p = g_cntpart[i];
            int c1 = (int)(p & 0xffffu), c2 = (int)(p >> 16);
            if (i < 1152) { c00 += c1; c01 += c2; }
            else          { c10 += c1; c11 += c2; }
        }
        #pragma unroll
        for (int off = 16; off; off >>= 1) {
            c00 += __shfl_down_sync(0xffffffffu, c00, off);
            c01 += __shfl_down_sync(0xffffffffu, c01, off);
            c10 += __shfl_down_sync(0xffffffffu, c10, off);
            c11 += __shfl_down_sync(0xffffffffu, c11, off);
        }
        if ((threadIdx.x & 31) == 0) {
            atomicAdd(&red[0], c00); atomicAdd(&red[1], c01);
            atomicAdd(&red[2], c10); atomicAdd(&red[3], c11);
        }
        __syncthreads();
        if (threadIdx.x == 0) {
            g_cnt[0] = red[0]; g_cnt[1] = red[1];
            g_cnt[2] = red[2]; g_cnt[3] = red[3];
            g_sum = 0ULL;
        }
    }

    int vb = bid / 288, rem = bid % 288;
    int s = rem / 3, wc = rem % 3;
    size_t base = (size_t)vb * N3 + (size_t)s * N2 + wc * 32;
    int tx = threadIdx.x & 31, ty = threadIdx.x >> 5;   // ty in [0,16)

    int mx0 = 0, mx1 = 0;
    #pragma unroll
    for (int r = ty; r < 96; r += 16) {
        unsigned u = g_pack[base + r * 96 + tx];
        int lo = (int)(u & 0xffffu), hi = (int)(u >> 16);
        mx0 = max(mx0, lo); mx1 = max(mx1, hi);
        float r2 = (float)(r * r);
        sh0[r * 32 + tx] = (float)lo + r2;
        sh1[r * 32 + tx] = (float)hi + r2;
    }
    #pragma unroll
    for (int off = 16; off; off >>= 1) {
        mx0 = max(mx0, __shfl_xor_sync(0xffffffffu, mx0, off));
        mx1 = max(mx1, __shfl_xor_sync(0xffffffffu, mx1, off));
    }
    if (tx == 0) { atomicMax(&smx0, mx0); atomicMax(&smx1, mx1); }
    __syncthreads();
    int R = max(win_i(smx0), win_i(smx1));

    int i0 = ty * 6;
    int j0 = max(0, i0 - R), j1 = min(95, i0 + 5 + R);
    float v0[6], v1[6], fi[6];
    #pragma unroll
    for (int k = 0; k < 6; k++) { v0[k] = 3.0e38f; v1[k] = 3.0e38f; fi[k] = (float)(i0 + k); }

    {
        const float* s0 = sh0 + tx;
        const float* s1 = sh1 + tx;
        float m2a = -2.0f * (float)j0;
        int j = j0;
        for (; j + 1 <= j1; j += 2) {
            float a0 = s0[j * 32], a1 = s1[j * 32];
            float b0 = s0[j * 32 + 32], b1 = s1[j * 32 + 32];
            float m2b = m2a - 2.0f;
            #pragma unroll
            for (int k = 0; k < 6; k++) {
                v0[k] = fminf(v0[k], fmaf(m2a, fi[k], a0));
                v1[k] = fminf(v1[k], fmaf(m2a, fi[k], a1));
                v0[k] = fminf(v0[k], fmaf(m2b, fi[k], b0));
                v1[k] = fminf(v1[k], fmaf(m2b, fi[k], b1));
            }
            m2a -= 4.0f;
        }
        if (j == j1) {
            float a0 = s0[j * 32], a1 = s1[j * 32];
            #pragma unroll
            for (int k = 0; k < 6; k++) {
                v0[k] = fminf(v0[k], fmaf(m2a, fi[k], a0));
                v1[k] = fminf(v1[k], fmaf(m2a, fi[k], a1));
            }
        }
    }

    unsigned* outp = g_pack + base + (size_t)i0 * 96 + tx;
    #pragma unroll
    for (int k = 0; k < 6; k++) {
        float i2 = fi[k] * fi[k];
        float r0 = v0[k] + i2;
        float r1 = v1[k] + i2;
        unsigned e0 = (r0 >= THRSF) ? (unsigned)SENTI : (unsigned)__float2int_rn(r0);
        unsigned e1 = (r1 >= THRSF) ? (unsigned)SENTI : (unsigned)__float2int_rn(r1);
        outp[k * 96] = e0 | (e1 << 16);
    }
}

// ------------------------------------------- fused D pass + softmax reduce
// Grid: 4 packed vols (b,cls) * 96 h-slices * 3 w-chunks = 1152 blocks x 512.
// Deterministic global accumulate: fixed-point (x 2^24) u64 atomic; the last
// block (ticket mod 1152) converts and writes the scalar output.
__global__ void __launch_bounds__(512, 3) k_fuse_d(const float* __restrict__ logits,
                                                   float* __restrict__ outp) {
    __shared__ float sh0[96 * 32];
    __shared__ float sh1[96 * 32];
    __shared__ int smx0, smx1;
    __shared__ float swred[16];
    int bid = blockIdx.x;
    int vb = bid / 288, rem = bid % 288;
    int s = rem / 3, wc = rem % 3;
    int b = vb >> 1, cls = vb & 1;
    int tx = threadIdx.x & 31, ty = threadIdx.x >> 5;
    unsigned nbase = (unsigned)s * 96 + wc * 32 + tx;   // voxel idx: + d*N2

    if (threadIdx.x == 0) { smx0 = 0; smx1 = 0; }
    __syncthreads();

    const unsigned* p = g_pack + (size_t)vb * N3 + nbase;
    int mx0 = 0, mx1 = 0;
    #pragma unroll
    for (int r = ty; r < 96; r += 16) {
        unsigned u = p[(size_t)r * N2];
        int lo = (int)(u & 0xffffu), hi = (int)(u >> 16);
        mx0 = max(mx0, lo); mx1 = max(mx1, hi);
        float r2 = (float)(r * r);
        sh0[r * 32 + tx] = (float)lo + r2;
        sh1[r * 32 + tx] = (float)hi + r2;
    }
    #pragma unroll
    for (int off = 16; off; off >>= 1) {
        mx0 = max(mx0, __shfl_xor_sync(0xffffffffu, mx0, off));
        mx1 = max(mx1, __shfl_xor_sync(0xffffffffu, mx1, off));
    }
    if (tx == 0) { atomicMax(&smx0, mx0); atomicMax(&smx1, mx1); }
    __syncthreads();
    int R = max(win_i(smx0), win_i(smx1));

    int i0 = ty * 6;
    int j0 = max(0, i0 - R), j1 = min(95, i0 + 5 + R);
    float v0[6], v1[6], fi[6];
    #pragma unroll
    for (int k = 0; k < 6; k++) { v0[k] = 3.0e38f; v1[k] = 3.0e38f; fi[k] = (float)(i0 + k); }

    {
        const float* s0 = sh0 + tx;
        const float* s1 = sh1 + tx;
        float m2a = -2.0f * (float)j0;
        int j = j0;
        for (; j + 1 <= j1; j += 2) {
            float a0 = s0[j * 32], a1 = s1[j * 32];
            float b0 = s0[j * 32 + 32], b1 = s1[j * 32 + 32];
            float m2b = m2a - 2.0f;
            #pragma unroll
            for (int k = 0; k < 6; k++) {
                v0[k] = fminf(v0[k], fmaf(m2a, fi[k], a0));
                v1[k] = fminf(v1[k], fmaf(m2a, fi[k], a1));
                v0[k] = fminf(v0[k], fmaf(m2b, fi[k], b0));
                v1[k] = fminf(v1[k], fmaf(m2b, fi[k], b1));
            }
            m2a -= 4.0f;
        }
        if (j == j1) {
            float a0 = s0[j * 32], a1 = s1[j * 32];
            #pragma unroll
            for (int k = 0; k < 6; k++) {
                v0[k] = fminf(v0[k], fmaf(m2a, fi[k], a0));
                v1[k] = fminf(v1[k], fmaf(m2a, fi[k], a1));
            }
        }
    }

    // epilogue: sd = sqrt(neg) - sqrt(pos); softmax prob of this class; gate
    float gate = g_cnt[b * 2 + cls] > 0 ? 1.f : 0.f;
    const float* L = logits + (size_t)b * 3 * N3 + nbase + (size_t)i0 * N2;
    float acc = 0.f;
    #pragma unroll
    for (int k = 0; k < 6; k++) {
        float i2 = fi[k] * fi[k];
        float r0 = v0[k] + i2;
        float r1 = v1[k] + i2;
        float f0 = (r0 >= THRSF) ? 1e8f : r0;
        float f1 = (r1 >= THRSF) ? 1e8f : r1;
        float sd = sqrtf(f1) - sqrtf(f0);
        float l0 = L[0], l1 = L[(size_t)N3], l2 = L[(size_t)2 * N3];
        L += N2;
        float m = fmaxf(l0, fmaxf(l1, l2));
        float e0 = __expf(l0 - m), e1 = __expf(l1 - m), e2 = __expf(l2 - m);
        float ec = cls ? e2 : e1;
        acc += (ec / (e0 + e1 + e2)) * sd;
    }
    acc *= gate;

    #pragma unroll
    for (int off = 16; off; off >>= 1)
        acc += __shfl_down_sync(0xffffffffu, acc, off);
    if (tx == 0) swred[ty] = acc;
    __syncthreads();
    if (threadIdx.x == 0) {
        float t = 0.f;
        #pragma unroll
        for (int i = 0; i < 16; i++) t += swred[i];
        // exact power-of-two scale -> deterministic integer accumulation
        long long q = llrintf(t * 16777216.0f);
        atomicAdd(&g_sum, (unsigned long long)q);
        __threadfence();
        unsigned tk = atomicAdd(&g_tick, 1u);
        if ((tk % 1152u) == 1151u) {
            long long ssum = (long long)atomicAdd(&g_sum, 0ULL);
            outp[0] = (float)((double)ssum / 16777216.0 / (2.0 * (double)N3));
        }
    }
}

// ---------------------------------------------------------------- launch
extern "C" void kernel_launch(void* const* d_in, const int* in_sizes, int n_in,
                              void* d_out, int out_size) {
    const float* logits = (const float*)d_in[0];
    const void*  targets = d_in[1];
    float* out = (float*)d_out;
    (void)in_sizes; (void)n_in; (void)out_size;

    k_binw<<<2304, 256>>>(targets);
    k_pass_h<<<1152, 512>>>();
    k_fuse_d<<<1152, 512>>>(logits, out);
}

// round 10
// speedup vs baseline: 1.2761x; 1.1022x over previous
#include <cuda_runtime.h>
#include <math.h>

// BoundaryLoss: exact squared-EDT via separable min-convolution. 2 kernels:
// k_wh:     per (vol, d-slice, w-chunk): ballot targets -> W nearest-zero
//           distance (only this block's 32 w's) -> windowed H min-conv ->
//           packed u32 (pos|neg<<16) store. 1152 blocks (full parallelism).
// k_fuse_d: windowed D min-conv + softmax + signed-dist + deterministic
//           fixed-point reduction. Per-warp exact window radius everywhere.
// Shapes: B=2, C=3, D=H=W=96.

#define N2 9216           // 96*96
#define N3 884736         // 96^3
#define SENTI 65535
#define THRSF 32768.0f    // real <= 27075 < 32768 <= sentinel-derived

__device__ unsigned g_pack[4 * N3];    // 14.2 MB packed scratch (pos|neg<<16)
__device__ unsigned g_cntpart[384];    // per (vol, d-slice) mask counts
__device__ unsigned long long g_sum;   // fixed-point (x 2^24) loss numerator
__device__ unsigned g_tick = 0;        // monotonic ticket (mod 1152 per launch)

// ---------------------------------------------- nearest zero bit in 96 bits
__device__ __forceinline__ int near_zero_dist(unsigned z0, unsigned z1, unsigned z2,
                                              int w, int r) {
    unsigned lowm = (2u << r) - 1u;
    unsigned him  = 0xffffffffu << r;
    int dl = 1000, dr = 1000;
    if (w == 0) {
        unsigned u = z0 & lowm;
        if (u) dl = r - (31 - __clz(u));
        unsigned v = z0 & him;
        if (v)       dr = (__ffs(v) - 1) - r;
        else if (z1) dr = 32 - r + (__ffs(z1) - 1);
        else if (z2) dr = 64 - r + (__ffs(z2) - 1);
    } else if (w == 1) {
        unsigned u = z1 & lowm;
        if (u)       dl = r - (31 - __clz(u));
        else if (z0) dl = r + 1 + __clz(z0);
        unsigned v = z1 & him;
        if (v)       dr = (__ffs(v) - 1) - r;
        else if (z2) dr = 32 - r + (__ffs(z2) - 1);
    } else {
        unsigned u = z2 & lowm;
        if (u)       dl = r - (31 - __clz(u));
        else if (z1) dl = r + 1 + __clz(z1);
        else if (z0) dl = r + 33 + __clz(z0);
        unsigned v = z2 & him;
        if (v) dr = (__ffs(v) - 1) - r;
    }
    return min(dl, dr);
}

// --------------------------------------------------- fused W + H pass
// Grid: 1152 = vb(2b x 2cls)*288 + d-slice*3 + w-chunk ; 512 threads.
// Phase 1: warp per h-line (6 lines/warp): full-line ballots, W nearest-zero
//          distance at this block's 32 w positions, both polarities;
//          float tiles sh[w:32][h:96+pad] hold f + h^2.
// Phase 2: per-warp windowed min-conv along h; packed coalesced store.
__global__ void __launch_bounds__(512, 3) k_wh(const void* __restrict__ tptr) {
    __shared__ float sh0[32 * 97];
    __shared__ float sh1[32 * 97];
    __shared__ int scnt;
    int bid = blockIdx.x;
    int vb = bid / 288, rem = bid % 288;
    int s = rem / 3, wc = rem % 3;
    int b = vb >> 1, clsv = (vb & 1) + 1;
    int lane = threadIdx.x & 31, wid = threadIdx.x >> 5;   // 16 warps

    const int* t32 = (const int*)tptr;
    if (threadIdx.x == 0) scnt = 0;
    // dtype probe: int64 targets in [0,2] -> all odd int32 words zero
    int any = (threadIdx.x < 64) ? (t32[2 * threadIdx.x + 1] != 0) : 0;
    int is64 = !__syncthreads_or(any);   // also orders scnt init

    int tb = b * N3 + s * N2;
    int cnt = 0;
    #pragma unroll
    for (int k = 0; k < 6; k++) {
        int h = wid + 16 * k;
        int t0, t1, t2;
        if (!is64) {
            const int* T = t32 + tb + h * 96;
            t0 = T[lane]; t1 = T[lane + 32]; t2 = T[lane + 64];
        } else {
            const long long* T = (const long long*)tptr + tb + h * 96;
            t0 = (int)T[lane]; t1 = (int)T[lane + 32]; t2 = (int)T[lane + 64];
        }
        unsigned m0 = __ballot_sync(0xffffffffu, t0 == clsv);
        unsigned m1 = __ballot_sync(0xffffffffu, t1 == clsv);
        unsigned m2 = __ballot_sync(0xffffffffu, t2 == clsv);
        if (wc == 0) cnt += __popc(m0) + __popc(m1) + __popc(m2);
        int dp = near_zero_dist(~m0, ~m1, ~m2, wc, lane);
        int dn = near_zero_dist(m0, m1, m2, wc, lane);
        int h2 = h * h;
        sh0[lane * 97 + h] = (float)(((dp > 95) ? SENTI : dp * dp) + h2);
        sh1[lane * 97 + h] = (float)(((dn > 95) ? SENTI : dn * dn) + h2);
    }
    if (wc == 0 && lane == 0) atomicAdd(&scnt, cnt);
    __syncthreads();
    if (wc == 0 && threadIdx.x == 0) g_cntpart[vb * 96 + s] = (unsigned)scnt;
    if (bid == 0 && threadIdx.x == 0) g_sum = 0ULL;

    // phase 2: min-conv along h for this thread's 6 outputs at w-row tx
    int tx = lane, ty = wid;
    int i0 = ty * 6;
    const float* s0 = sh0 + tx * 97;
    const float* s1 = sh1 + tx * 97;

    float fi[6];
    #pragma unroll
    for (int k = 0; k < 6; k++) fi[k] = (float)(i0 + k);

    // per-warp exact window: R >= sqrt(f[i]) for every output in the warp
    float fm = 0.f;
    #pragma unroll
    for (int k = 0; k < 6; k++) {
        float i2 = fi[k] * fi[k];
        fm = fmaxf(fm, fmaxf(s0[i0 + k], s1[i0 + k]) - i2);
    }
    #pragma unroll
    for (int off = 16; off; off >>= 1)
        fm = fmaxf(fm, __shfl_xor_sync(0xffffffffu, fm, off));
    int R = (fm >= THRSF) ? 95 : min(95, (int)floorf(sqrtf(fm)) + 1);

    int j0 = max(0, i0 - R), j1 = min(95, i0 + 5 + R);
    float v0[6], v1[6];
    #pragma unroll
    for (int k = 0; k < 6; k++) { v0[k] = 3.0e38f; v1[k] = 3.0e38f; }

    float m2a = -2.0f * (float)j0;
    int j = j0;
    for (; j + 1 <= j1; j += 2) {
        float a0 = s0[j], a1 = s1[j];
        float b0 = s0[j + 1], b1 = s1[j + 1];
        float m2b = m2a - 2.0f;
        #pragma unroll
        for (int k = 0; k < 6; k++) {
            v0[k] = fminf(v0[k], fmaf(m2a, fi[k], a0));
            v1[k] = fminf(v1[k], fmaf(m2a, fi[k], a1));
            v0[k] = fminf(v0[k], fmaf(m2b, fi[k], b0));
            v1[k] = fminf(v1[k], fmaf(m2b, fi[k], b1));
        }
        m2a -= 4.0f;
    }
    if (j == j1) {
        float a0 = s0[j], a1 = s1[j];
        #pragma unroll
        for (int k = 0; k < 6; k++) {
            v0[k] = fminf(v0[k], fmaf(m2a, fi[k], a0));
            v1[k] = fminf(v1[k], fmaf(m2a, fi[k], a1));
        }
    }

    unsigned* outp = g_pack + (size_t)vb * N3 + (size_t)s * N2 + wc * 32 + tx;
    #pragma unroll
    for (int k = 0; k < 6; k++) {
        float i2 = fi[k] * fi[k];
        float r0 = v0[k] + i2;
        float r1 = v1[k] + i2;
        unsigned e0 = (r0 >= THRSF) ? (unsigned)SENTI : (unsigned)__float2int_rn(r0);
        unsigned e1 = (r1 >= THRSF) ? (unsigned)SENTI : (unsigned)__float2int_rn(r1);
        outp[(size_t)(i0 + k) * 96] = e0 | (e1 << 16);
    }
}

// ------------------------------------------- fused D pass + softmax reduce
// Grid: 4 packed vols (b,cls) * 96 h-slices * 3 w-chunks = 1152 blocks x 512.
__global__ void __launch_bounds__(512, 3) k_fuse_d(const float* __restrict__ logits,
                                                   float* __restrict__ outp) {
    __shared__ float sh0[96 * 32];
    __shared__ float sh1[96 * 32];
    __shared__ float swred[16];
    int bid = blockIdx.x;
    int vb = bid / 288, rem = bid % 288;
    int s = rem / 3, wc = rem % 3;
    int b = vb >> 1, cls = vb & 1;
    int tx = threadIdx.x & 31, ty = threadIdx.x >> 5;
    unsigned nbase = (unsigned)s * 96 + wc * 32 + tx;   // voxel idx: + d*N2

    // gate = mask.any() for this (b, cls): OR over its 96 per-slice counts
    int pred = (threadIdx.x < 96) ? (g_cntpart[vb * 96 + threadIdx.x] != 0) : 0;
    float gate = __syncthreads_or(pred) ? 1.f : 0.f;

    const unsigned* p = g_pack + (size_t)vb * N3 + nbase;
    #pragma unroll
    for (int r = ty; r < 96; r += 16) {
        unsigned u = p[(size_t)r * N2];
        float r2 = (float)(r * r);
        sh0[r * 32 + tx] = (float)(u & 0xffffu) + r2;
        sh1[r * 32 + tx] = (float)(u >> 16) + r2;
    }
    __syncthreads();

    int i0 = ty * 6;
    float fi[6];
    #pragma unroll
    for (int k = 0; k < 6; k++) fi[k] = (float)(i0 + k);

    const float* s0 = sh0 + tx;
    const float* s1 = sh1 + tx;

    // per-warp exact window radius
    float fm = 0.f;
    #pragma unroll
    for (int k = 0; k < 6; k++) {
        float i2 = fi[k] * fi[k];
        fm = fmaxf(fm, fmaxf(s0[(i0 + k) * 32], s1[(i0 + k) * 32]) - i2);
    }
    #pragma unroll
    for (int off = 16; off; off >>= 1)
        fm = fmaxf(fm, __shfl_xor_sync(0xffffffffu, fm, off));
    int R = (fm >= THRSF) ? 95 : min(95, (int)floorf(sqrtf(fm)) + 1);

    int j0 = max(0, i0 - R), j1 = min(95, i0 + 5 + R);
    float v0[6], v1[6];
    #pragma unroll
    for (int k = 0; k < 6; k++) { v0[k] = 3.0e38f; v1[k] = 3.0e38f; }

    float m2a = -2.0f * (float)j0;
    int j = j0;
    for (; j + 1 <= j1; j += 2) {
        float a0 = s0[j * 32], a1 = s1[j * 32];
        float b0 = s0[j * 32 + 32], b1 = s1[j * 32 + 32];
        float m2b = m2a - 2.0f;
        #pragma unroll
        for (int k = 0; k < 6; k++) {
            v0[k] = fminf(v0[k], fmaf(m2a, fi[k], a0));
            v1[k] = fminf(v1[k], fmaf(m2a, fi[k], a1));
            v0[k] = fminf(v0[k], fmaf(m2b, fi[k], b0));
            v1[k] = fminf(v1[k], fmaf(m2b, fi[k], b1));
        }
        m2a -= 4.0f;
    }
    if (j == j1) {
        float a0 = s0[j * 32], a1 = s1[j * 32];
        #pragma unroll
        for (int k = 0; k < 6; k++) {
            v0[k] = fminf(v0[k], fmaf(m2a, fi[k], a0));
            v1[k] = fminf(v1[k], fmaf(m2a, fi[k], a1));
        }
    }

    // epilogue: sd = sqrt(neg) - sqrt(pos); softmax prob of this class; gate
    const float* L = logits + (size_t)b * 3 * N3 + nbase + (size_t)i0 * N2;
    float acc = 0.f;
    #pragma unroll
    for (int k = 0; k < 6; k++) {
        float i2 = fi[k] * fi[k];
        float r0 = v0[k] + i2;
        float r1 = v1[k] + i2;
        float f0 = (r0 >= THRSF) ? 1e8f : r0;
        float f1 = (r1 >= THRSF) ? 1e8f : r1;
        float sd = sqrtf(f1) - sqrtf(f0);
        float l0 = L[0], l1 = L[(size_t)N3], l2 = L[(size_t)2 * N3];
        L += N2;
        float m = fmaxf(l0, fmaxf(l1, l2));
        float e0 = __expf(l0 - m), e1 = __expf(l1 - m), e2 = __expf(l2 - m);
        float ec = cls ? e2 : e1;
        acc += (ec / (e0 + e1 + e2)) * sd;
    }
    acc *= gate;

    #pragma unroll
    for (int off = 16; off; off >>= 1)
        acc += __shfl_down_sync(0xffffffffu, acc, off);
    if (tx == 0) swred[ty] = acc;
    __syncthreads();
    if (threadIdx.x == 0) {
        float t = 0.f;
        #pragma unroll
        for (int i = 0; i < 16; i++) t += swred[i];
        // exact power-of-two scale -> deterministic integer accumulation
        long long q = llrintf(t * 16777216.0f);
        atomicAdd(&g_sum, (unsigned long long)q);
        __threadfence();
        unsigned tk = atomicAdd(&g_tick, 1u);
        if ((tk % 1152u) == 1151u) {
            long long ssum = (long long)atomicAdd(&g_sum, 0ULL);
            outp[0] = (float)((double)ssum / 16777216.0 / (2.0 * (double)N3));
        }
    }
}

// ---------------------------------------------------------------- launch
extern "C" void kernel_launch(void* const* d_in, const int* in_sizes, int n_in,
                              void* d_out, int out_size) {
    const float* logits = (const float*)d_in[0];
    const void*  targets = d_in[1];
    float* out = (float*)d_out;
    (void)in_sizes; (void)n_in; (void)out_size;

    k_wh<<<1152, 512>>>(targets);
    k_fuse_d<<<1152, 512>>>(logits, out);
}

// round 11
// speedup vs baseline: 1.3335x; 1.0450x over previous
#include <cuda_runtime.h>
#include <math.h>

// BoundaryLoss: exact squared-EDT via separable min-convolution. 2 kernels:
// k_wh:     per (vol, d-slice, w-chunk): ballot targets -> W nearest-zero
//           distance -> windowed H min-conv -> packed u32 store.
// k_fuse_d: windowed D min-conv + softmax + signed-dist + deterministic
//           fixed-point reduction. float2 smem tiles, per-warp windows.
// Shapes: B=2, C=3, D=H=W=96.

#define N2 9216           // 96*96
#define N3 884736         // 96^3
#define SENTI 65535
#define THRSF 32768.0f    // real <= 27075 < 32768 <= sentinel-derived

__device__ unsigned g_pack[4 * N3];    // 14.2 MB packed scratch (pos|neg<<16)
__device__ unsigned g_cntpart[384];    // per (vol, d-slice) mask counts
__device__ unsigned long long g_sum;   // fixed-point (x 2^24) loss numerator
__device__ unsigned g_tick = 0;        // monotonic ticket (mod 1152 per launch)

// ---------------------------------------------- nearest zero bit in 96 bits
__device__ __forceinline__ int near_zero_dist(unsigned z0, unsigned z1, unsigned z2,
                                              int w, int r) {
    unsigned lowm = (2u << r) - 1u;
    unsigned him  = 0xffffffffu << r;
    int dl = 1000, dr = 1000;
    if (w == 0) {
        unsigned u = z0 & lowm;
        if (u) dl = r - (31 - __clz(u));
        unsigned v = z0 & him;
        if (v)       dr = (__ffs(v) - 1) - r;
        else if (z1) dr = 32 - r + (__ffs(z1) - 1);
        else if (z2) dr = 64 - r + (__ffs(z2) - 1);
    } else if (w == 1) {
        unsigned u = z1 & lowm;
        if (u)       dl = r - (31 - __clz(u));
        else if (z0) dl = r + 1 + __clz(z0);
        unsigned v = z1 & him;
        if (v)       dr = (__ffs(v) - 1) - r;
        else if (z2) dr = 32 - r + (__ffs(z2) - 1);
    } else {
        unsigned u = z2 & lowm;
        if (u)       dl = r - (31 - __clz(u));
        else if (z1) dl = r + 1 + __clz(z1);
        else if (z0) dl = r + 33 + __clz(z0);
        unsigned v = z2 & him;
        if (v) dr = (__ffs(v) - 1) - r;
    }
    return min(dl, dr);
}

// --------------------------------------------------- fused W + H pass
// Grid: 1152 = vb(2b x 2cls)*288 + d-slice*3 + w-chunk ; 512 threads.
__global__ void __launch_bounds__(512, 3) k_wh(const void* __restrict__ tptr) {
    __shared__ float2 sh[32 * 97];     // [w-row][h], pitch 97: bank = tx + j
    __shared__ int scnt;
    int bid = blockIdx.x;
    int vb = bid / 288, rem = bid % 288;
    int s = rem / 3, wc = rem % 3;
    int b = vb >> 1, clsv = (vb & 1) + 1;
    int lane = threadIdx.x & 31, wid = threadIdx.x >> 5;   // 16 warps

    const int* t32 = (const int*)tptr;
    if (threadIdx.x == 0) scnt = 0;
    // dtype probe: int64 targets in [0,2] -> all odd int32 words zero
    int any = (threadIdx.x < 64) ? (t32[2 * threadIdx.x + 1] != 0) : 0;
    int is64 = !__syncthreads_or(any);   // also orders scnt init

    int tb = b * N3 + s * N2;
    int cnt = 0;
    #pragma unroll
    for (int k = 0; k < 6; k++) {
        int h = wid + 16 * k;
        int t0, t1, t2;
        if (!is64) {
            const int* T = t32 + tb + h * 96;
            t0 = T[lane]; t1 = T[lane + 32]; t2 = T[lane + 64];
        } else {
            const long long* T = (const long long*)tptr + tb + h * 96;
            t0 = (int)T[lane]; t1 = (int)T[lane + 32]; t2 = (int)T[lane + 64];
        }
        unsigned m0 = __ballot_sync(0xffffffffu, t0 == clsv);
        unsigned m1 = __ballot_sync(0xffffffffu, t1 == clsv);
        unsigned m2 = __ballot_sync(0xffffffffu, t2 == clsv);
        if (wc == 0) cnt += __popc(m0) + __popc(m1) + __popc(m2);
        int dp = near_zero_dist(~m0, ~m1, ~m2, wc, lane);
        int dn = near_zero_dist(m0, m1, m2, wc, lane);
        int h2 = h * h;
        sh[lane * 97 + h] = make_float2(
            (float)(((dp > 95) ? SENTI : dp * dp) + h2),
            (float)(((dn > 95) ? SENTI : dn * dn) + h2));
    }
    if (wc == 0 && lane == 0) atomicAdd(&scnt, cnt);
    __syncthreads();
    if (wc == 0 && threadIdx.x == 0) g_cntpart[vb * 96 + s] = (unsigned)scnt;
    if (bid == 0 && threadIdx.x == 0) g_sum = 0ULL;

    // phase 2: min-conv along h for this thread's 6 outputs at w-row tx
    int tx = lane, ty = wid;
    int i0 = ty * 6;
    const float2* sp = sh + tx * 97;

    float fi[6];
    #pragma unroll
    for (int k = 0; k < 6; k++) fi[k] = (float)(i0 + k);

    // per-warp exact window: R >= sqrt(f[i]) for every output in the warp
    float fm = 0.f;
    #pragma unroll
    for (int k = 0; k < 6; k++) {
        float i2 = fi[k] * fi[k];
        float2 u = sp[i0 + k];
        fm = fmaxf(fm, fmaxf(u.x, u.y) - i2);
    }
    #pragma unroll
    for (int off = 16; off; off >>= 1)
        fm = fmaxf(fm, __shfl_xor_sync(0xffffffffu, fm, off));
    int R = (fm >= THRSF) ? 95 : min(95, (int)floorf(sqrtf(fm)) + 1);

    int j0 = max(0, i0 - R), j1 = min(95, i0 + 5 + R);
    float v0[6], v1[6];
    #pragma unroll
    for (int k = 0; k < 6; k++) { v0[k] = 3.0e38f; v1[k] = 3.0e38f; }

    float m2a = -2.0f * (float)j0;
    int j = j0;
    for (; j + 1 <= j1; j += 2) {
        float2 a = sp[j], bb = sp[j + 1];
        float m2b = m2a - 2.0f;
        #pragma unroll
        for (int k = 0; k < 6; k++) {
            v0[k] = fminf(v0[k], fmaf(m2a, fi[k], a.x));
            v1[k] = fminf(v1[k], fmaf(m2a, fi[k], a.y));
            v0[k] = fminf(v0[k], fmaf(m2b, fi[k], bb.x));
            v1[k] = fminf(v1[k], fmaf(m2b, fi[k], bb.y));
        }
        m2a -= 4.0f;
    }
    if (j == j1) {
        float2 a = sp[j];
        #pragma unroll
        for (int k = 0; k < 6; k++) {
            v0[k] = fminf(v0[k], fmaf(m2a, fi[k], a.x));
            v1[k] = fminf(v1[k], fmaf(m2a, fi[k], a.y));
        }
    }

    unsigned* outp = g_pack + (size_t)vb * N3 + (size_t)s * N2 + wc * 32 + tx;
    #pragma unroll
    for (int k = 0; k < 6; k++) {
        float i2 = fi[k] * fi[k];
        float r0 = v0[k] + i2;
        float r1 = v1[k] + i2;
        unsigned e0 = (r0 >= THRSF) ? (unsigned)SENTI : (unsigned)__float2int_rn(r0);
        unsigned e1 = (r1 >= THRSF) ? (unsigned)SENTI : (unsigned)__float2int_rn(r1);
        outp[(size_t)(i0 + k) * 96] = e0 | (e1 << 16);
    }
}

// ------------------------------------------- fused D pass + softmax reduce
// Grid: 4 packed vols (b,cls) * 96 h-slices * 3 w-chunks = 1152 blocks x 512.
__global__ void __launch_bounds__(512, 4) k_fuse_d(const float* __restrict__ logits,
                                                   float* __restrict__ outp) {
    __shared__ float2 sh[96 * 32];     // 24.6 KB: [d-row][w], 64-bit conflict-free
    __shared__ float swred[16];
    int bid = blockIdx.x;
    int vb = bid / 288, rem = bid % 288;
    int s = rem / 3, wc = rem % 3;
    int b = vb >> 1, cls = vb & 1;
    int tx = threadIdx.x & 31, ty = threadIdx.x >> 5;
    unsigned nbase = (unsigned)s * 96 + wc * 32 + tx;   // voxel idx: + d*N2

    // gate = mask.any() for this (b, cls): OR over its 96 per-slice counts
    int pred = (threadIdx.x < 96) ? (g_cntpart[vb * 96 + threadIdx.x] != 0) : 0;
    float gate = __syncthreads_or(pred) ? 1.f : 0.f;

    const unsigned* p = g_pack + (size_t)vb * N3 + nbase;
    #pragma unroll
    for (int r = ty; r < 96; r += 16) {
        unsigned u = p[(size_t)r * N2];
        float r2 = (float)(r * r);
        sh[r * 32 + tx] = make_float2((float)(u & 0xffffu) + r2,
                                      (float)(u >> 16) + r2);
    }
    __syncthreads();

    int i0 = ty * 6;
    float fi[6];
    #pragma unroll
    for (int k = 0; k < 6; k++) fi[k] = (float)(i0 + k);

    const float2* sp = sh + tx;

    // per-warp exact window radius
    float fm = 0.f;
    #pragma unroll
    for (int k = 0; k < 6; k++) {
        float i2 = fi[k] * fi[k];
        float2 u = sp[(i0 + k) * 32];
        fm = fmaxf(fm, fmaxf(u.x, u.y) - i2);
    }
    #pragma unroll
    for (int off = 16; off; off >>= 1)
        fm = fmaxf(fm, __shfl_xor_sync(0xffffffffu, fm, off));
    int R = (fm >= THRSF) ? 95 : min(95, (int)floorf(sqrtf(fm)) + 1);

    int j0 = max(0, i0 - R), j1 = min(95, i0 + 5 + R);
    float v0[6], v1[6];
    #pragma unroll
    for (int k = 0; k < 6; k++) { v0[k] = 3.0e38f; v1[k] = 3.0e38f; }

    float m2a = -2.0f * (float)j0;
    int j = j0;
    for (; j + 1 <= j1; j += 2) {
        float2 a = sp[j * 32], bb = sp[j * 32 + 32];
        float m2b = m2a - 2.0f;
        #pragma unroll
        for (int k = 0; k < 6; k++) {
            v0[k] = fminf(v0[k], fmaf(m2a, fi[k], a.x));
            v1[k] = fminf(v1[k], fmaf(m2a, fi[k], a.y));
            v0[k] = fminf(v0[k], fmaf(m2b, fi[k], bb.x));
            v1[k] = fminf(v1[k], fmaf(m2b, fi[k], bb.y));
        }
        m2a -= 4.0f;
    }
    if (j == j1) {
        float2 a = sp[j * 32];
        #pragma unroll
        for (int k = 0; k < 6; k++) {
            v0[k] = fminf(v0[k], fmaf(m2a, fi[k], a.x));
            v1[k] = fminf(v1[k], fmaf(m2a, fi[k], a.y));
        }
    }

    // epilogue: sd = sqrt(neg) - sqrt(pos); softmax prob of this class; gate
    const float* L = logits + (size_t)b * 3 * N3 + nbase + (size_t)i0 * N2;
    float acc = 0.f;
    #pragma unroll
    for (int k = 0; k < 6; k++) {
        float i2 = fi[k] * fi[k];
        float r0 = v0[k] + i2;
        float r1 = v1[k] + i2;
        float f0 = (r0 >= THRSF) ? 1e8f : r0;
        float f1 = (r1 >= THRSF) ? 1e8f : r1;
        float sd = sqrtf(f1) - sqrtf(f0);
        float l0 = L[0], l1 = L[(size_t)N3], l2 = L[(size_t)2 * N3];
        L += N2;
        float m = fmaxf(l0, fmaxf(l1, l2));
        float e0 = __expf(l0 - m), e1 = __expf(l1 - m), e2 = __expf(l2 - m);
        float ec = cls ? e2 : e1;
        acc += ec * __fdividef(sd, e0 + e1 + e2);
    }
    acc *= gate;

    #pragma unroll
    for (int off = 16; off; off >>= 1)
        acc += __shfl_down_sync(0xffffffffu, acc, off);
    if (tx == 0) swred[ty] = acc;
    __syncthreads();
    if (threadIdx.x == 0) {
        float t = 0.f;
        #pragma unroll
        for (int i = 0; i < 16; i++) t += swred[i];
        // exact power-of-two scale -> deterministic integer accumulation
        long long q = llrintf(t * 16777216.0f);
        atomicAdd(&g_sum, (unsigned long long)q);
        __threadfence();
        unsigned tk = atomicAdd(&g_tick, 1u);
        if ((tk % 1152u) == 1151u) {
            long long ssum = (long long)atomicAdd(&g_sum, 0ULL);
            outp[0] = (float)((double)ssum / 16777216.0 / (2.0 * (double)N3));
        }
    }
}

// ---------------------------------------------------------------- launch
extern "C" void kernel_launch(void* const* d_in, const int* in_sizes, int n_in,
                              void* d_out, int out_size) {
    const float* logits = (const float*)d_in[0];
    const void*  targets = d_in[1];
    float* out = (float*)d_out;
    (void)in_sizes; (void)n_in; (void)out_size;

    k_wh<<<1152, 512>>>(targets);
    k_fuse_d<<<1152, 512>>>(logits, out);
}